// round 1
// baseline (speedup 1.0000x reference)
#include <cuda_runtime.h>
#include <math.h>

// Problem constants (fixed by the dataset)
#define BATCH 512
#define DIM   128      // input / output feature dim
#define HID   1024     // LSTM hidden
#define GATES 4096     // 4*HID
#define KTOT  1152     // DIM + HID (fused [x,h] GEMM)

// ---------------- device scratch (no allocs allowed) ----------------
// Gate-interleaved, K-major packed weights: g_Wt[k][4*j + gate]
__device__ float g_Wt[KTOT * GATES];        // 18.9 MB
__device__ float g_b2[GATES];               // b_ih + b_hh, gate-interleaved
__device__ float g_WoutT[HID * DIM];        // W_out^T, K-major
__device__ float g_h[2][BATCH * HID];       // double-buffered hidden state
__device__ float g_c[BATCH * HID];          // cell state (owner-updated in place)

// ---------------- packing kernels ----------------
__global__ void pack_w_kernel(const float* __restrict__ W_ih,
                              const float* __restrict__ W_hh) {
    int idx = blockIdx.x * blockDim.x + threadIdx.x;
    if (idx >= KTOT * GATES) return;
    int k  = idx / GATES;
    int np = idx - k * GATES;     // n' = 4*j + gate
    int j = np >> 2, g = np & 3;
    int n = g * HID + j;          // original PyTorch gate row (i,f,g,o blocks)
    float v = (k < DIM) ? W_ih[n * DIM + k] : W_hh[n * HID + (k - DIM)];
    g_Wt[idx] = v;
}

__global__ void setup_kernel(const float* __restrict__ b_ih,
                             const float* __restrict__ b_hh,
                             const float* __restrict__ W_out) {
    int idx = blockIdx.x * blockDim.x + threadIdx.x;
    if (idx < GATES) {
        int j = idx >> 2, g = idx & 3;
        int n = g * HID + j;
        g_b2[idx] = b_ih[n] + b_hh[n];
    }
    if (idx < HID * DIM) {
        int k = idx / DIM, d = idx - k * DIM;
        g_WoutT[idx] = W_out[d * HID + k];
    }
    if (idx < BATCH * HID) {
        g_h[0][idx] = 0.f;
        g_c[idx]    = 0.f;
    }
}

// ---------------- fused LSTM step: gates = [x,h] @ Wcat^T + b ; cell update ----------------
#define BM 64
#define BN 128
#define BK 16

__device__ __forceinline__ float sigm(float v) { return 1.f / (1.f + expf(-v)); }

__global__ __launch_bounds__(256, 2)
void lstm_step_kernel(const float* __restrict__ x, int xstride, int sel) {
    __shared__ float As[BK][BM];
    __shared__ float Bs[BK][BN];

    const float* __restrict__ hin  = g_h[sel];
    float*       __restrict__ hout = g_h[sel ^ 1];

    int tid = threadIdx.x;
    int tm = tid >> 5;          // 0..7  (8 m-groups of 8 rows)
    int tn = tid & 31;          // 0..31 (each owns 4 consecutive n' = 4 gates of one j)
    int m0 = blockIdx.y * BM;
    int n0 = blockIdx.x * BN;

    // A tile loader: 64x16 floats, one float4 per thread
    int am = tid >> 2;          // 0..63
    int ak = (tid & 3) * 4;     // 0,4,8,12
    // B tile loader: 16x128 floats, two float4 per thread
    int bk = tid >> 5;          // 0..7
    int bn = (tid & 31) * 4;

    float acc[8][4];
#pragma unroll
    for (int r = 0; r < 8; r++)
#pragma unroll
        for (int c2 = 0; c2 < 4; c2++) acc[r][c2] = 0.f;

    const float* __restrict__ Wp = g_Wt + n0;

    for (int k0 = 0; k0 < KTOT; k0 += BK) {
        // choose A source region (x for k<128, h for k>=128; BK never straddles 128)
        const float* abase; int astr;
        if (k0 < DIM) { abase = x + k0;           astr = xstride; }
        else          { abase = hin + (k0 - DIM); astr = HID;     }
        float4 av  = *(const float4*)(abase + (size_t)(m0 + am) * astr + ak);
        float4 bv0 = *(const float4*)(Wp + (size_t)(k0 + bk)     * GATES + bn);
        float4 bv1 = *(const float4*)(Wp + (size_t)(k0 + bk + 8) * GATES + bn);

        __syncthreads();
        As[ak + 0][am] = av.x;
        As[ak + 1][am] = av.y;
        As[ak + 2][am] = av.z;
        As[ak + 3][am] = av.w;
        *(float4*)&Bs[bk][bn]     = bv0;
        *(float4*)&Bs[bk + 8][bn] = bv1;
        __syncthreads();

#pragma unroll
        for (int kk = 0; kk < BK; kk++) {
            float a[8], b[4];
            *(float4*)&a[0] = *(const float4*)&As[kk][tm * 8];
            *(float4*)&a[4] = *(const float4*)&As[kk][tm * 8 + 4];
            *(float4*)&b[0] = *(const float4*)&Bs[kk][tn * 4];
#pragma unroll
            for (int r = 0; r < 8; r++)
#pragma unroll
                for (int c2 = 0; c2 < 4; c2++)
                    acc[r][c2] += a[r] * b[c2];
        }
    }

    // Epilogue: LSTM cell. Each thread owns gates (i,f,g,o) of hidden unit j for 8 rows.
    int j = (n0 >> 2) + tn;
    float4 bb = *(const float4*)&g_b2[n0 + tn * 4];
#pragma unroll
    for (int r = 0; r < 8; r++) {
        int m = m0 + tm * 8 + r;
        float gi = acc[r][0] + bb.x;
        float gf = acc[r][1] + bb.y;
        float gg = acc[r][2] + bb.z;
        float go = acc[r][3] + bb.w;
        size_t off = (size_t)m * HID + j;
        float cold = g_c[off];
        float cn = sigm(gf) * cold + sigm(gi) * tanhf(gg);
        float hn = sigm(go) * tanhf(cn);
        g_c[off]  = cn;
        hout[off] = hn;
    }
}

// ---------------- decode output projection: out = h @ W_out^T + b_out ----------------
#define OBM 16
#define OBN 32
#define OBK 16

__global__ __launch_bounds__(128)
void out_proj_kernel(int sel, const float* __restrict__ b_out,
                     float* __restrict__ out, int ostride) {
    __shared__ float As[OBK][OBM];
    __shared__ float Bs[OBK][OBN];

    const float* __restrict__ hin = g_h[sel];

    int tid = threadIdx.x;
    int tm = tid >> 3;       // 0..15 (one m row each)
    int tn = tid & 7;        // 0..7  (4 n cols each)
    int m0 = blockIdx.y * OBM;
    int n0 = blockIdx.x * OBN;

    // A loader: 16x16, float2 per thread
    int a_m  = tid >> 3;          // 0..15
    int a_k2 = (tid & 7) * 2;     // 0..14
    // B loader: 16x32, 4 scalars per thread
    int b_k = tid >> 5;           // 0..3
    int b_n = tid & 31;

    float acc[4] = {0.f, 0.f, 0.f, 0.f};

    for (int k0 = 0; k0 < HID; k0 += OBK) {
        float2 av = *(const float2*)(hin + (size_t)(m0 + a_m) * HID + k0 + a_k2);
        float bv[4];
#pragma unroll
        for (int i = 0; i < 4; i++)
            bv[i] = g_WoutT[(size_t)(k0 + b_k + 4 * i) * DIM + n0 + b_n];

        __syncthreads();
        As[a_k2][a_m]     = av.x;
        As[a_k2 + 1][a_m] = av.y;
#pragma unroll
        for (int i = 0; i < 4; i++) Bs[b_k + 4 * i][b_n] = bv[i];
        __syncthreads();

#pragma unroll
        for (int kk = 0; kk < OBK; kk++) {
            float a = As[kk][tm];
            float b[4];
            *(float4*)&b[0] = *(const float4*)&Bs[kk][tn * 4];
#pragma unroll
            for (int c2 = 0; c2 < 4; c2++) acc[c2] += a * b[c2];
        }
    }

#pragma unroll
    for (int c2 = 0; c2 < 4; c2++) {
        int n = n0 + tn * 4 + c2;
        out[(size_t)(m0 + tm) * ostride + n] = acc[c2] + b_out[n];
    }
}

// ---------------- launch ----------------
extern "C" void kernel_launch(void* const* d_in, const int* in_sizes, int n_in,
                              void* d_out, int out_size) {
    const float* src   = (const float*)d_in[0];
    const float* W_ih  = (const float*)d_in[2];
    const float* W_hh  = (const float*)d_in[3];
    const float* b_ih  = (const float*)d_in[4];
    const float* b_hh  = (const float*)d_in[5];
    const float* W_out = (const float*)d_in[6];
    const float* b_out = (const float*)d_in[7];
    float* out = (float*)d_out;

    int srclen = in_sizes[0] / (BATCH * DIM);   // 240
    int tgtlen = in_sizes[1] / (BATCH * DIM);   // 24
    int sstride = srclen * DIM;
    int ostride = tgtlen * DIM;

    pack_w_kernel<<<(KTOT * GATES + 255) / 256, 256>>>(W_ih, W_hh);
    setup_kernel<<<(BATCH * HID + 255) / 256, 256>>>(b_ih, b_hh, W_out);

    dim3 sgrid(GATES / BN, BATCH / BM);   // (32, 8)
    dim3 ogrid(DIM / OBN, BATCH / OBM);   // (4, 32)

    int sel = 0;
    // Encoder: frames 0..srclen-2
    for (int t = 0; t < srclen - 1; t++) {
        lstm_step_kernel<<<sgrid, 256>>>(src + (size_t)t * DIM, sstride, sel);
        sel ^= 1;
    }
    // Decoder: seeded with last src frame, then autoregressive on own output
    for (int t = 0; t < tgtlen; t++) {
        const float* x;
        int xs;
        if (t == 0) { x = src + (size_t)(srclen - 1) * DIM; xs = sstride; }
        else        { x = out + (size_t)(t - 1) * DIM;      xs = ostride; }
        lstm_step_kernel<<<sgrid, 256>>>(x, xs, sel);
        sel ^= 1;  // g_h[sel] now holds the new hidden state
        out_proj_kernel<<<ogrid, 128>>>(sel, b_out, out + (size_t)t * DIM, ostride);
    }
}

// round 4
// speedup vs baseline: 1.7139x; 1.7139x over previous
#include <cuda_runtime.h>
#include <cuda_bf16.h>
#include <math.h>
#include <stdint.h>

#define BATCH 512
#define DIM   128
#define HID   1024
#define GATES 4096
#define KTOT  1152
#define MAXSRC 240
#define MAXTGT 24
#define NSTAGE 36            // K=1152 / 32
#define STG_BYTES 32768      // Ahi 8K | Alo 8K | Bhi 8K | Blo 8K
#define SMEM_REQ (4 * STG_BYTES)

typedef __nv_bfloat16 bf16;

// ---------------- device scratch (aligned for cp.async/vector access) ----------------
__device__ __align__(256) bf16  g_Whi[GATES * KTOT];      // [np][k] K-major, packed cols
__device__ __align__(256) bf16  g_Wlo[GATES * KTOT];
__device__ __align__(256) bf16  g_src_hi[MAXSRC * BATCH * DIM];
__device__ __align__(256) bf16  g_src_lo[MAXSRC * BATCH * DIM];
__device__ __align__(256) bf16  g_dec_hi[MAXTGT * BATCH * DIM];
__device__ __align__(256) bf16  g_dec_lo[MAXTGT * BATCH * DIM];
__device__ __align__(256) bf16  g_h_hi[2][BATCH * HID];
__device__ __align__(256) bf16  g_h_lo[2][BATCH * HID];
__device__ __align__(256) float g_c[BATCH * HID];
__device__ __align__(256) float g_b2[GATES];              // packed biases
__device__ __align__(256) float g_WoutT[HID * DIM];

// ---------------- helpers ----------------
__device__ __forceinline__ uint32_t smem_u32(const void* p) {
    uint32_t a;
    asm("{ .reg .u64 t; cvta.to.shared.u64 t, %1; cvt.u32.u64 %0, t; }" : "=r"(a) : "l"(p));
    return a;
}
__device__ __forceinline__ void cp16(uint32_t dst, const void* src) {
    asm volatile("cp.async.cg.shared.global [%0], [%1], 16;" :: "r"(dst), "l"(src));
}
__device__ __forceinline__ void cp_commit() { asm volatile("cp.async.commit_group;" ::: "memory"); }
template<int N> __device__ __forceinline__ void cp_wait() {
    asm volatile("cp.async.wait_group %0;" :: "n"(N) : "memory");
}
__device__ __forceinline__ void ldm4(uint32_t* r, uint32_t addr) {
    asm volatile("ldmatrix.sync.aligned.m8n8.x4.shared.b16 {%0,%1,%2,%3}, [%4];"
                 : "=r"(r[0]), "=r"(r[1]), "=r"(r[2]), "=r"(r[3]) : "r"(addr));
}
__device__ __forceinline__ void mma16816(float* c, const uint32_t* a, const uint32_t* b) {
    asm volatile(
        "mma.sync.aligned.m16n8k16.row.col.f32.bf16.bf16.f32 "
        "{%0,%1,%2,%3}, {%4,%5,%6,%7}, {%8,%9}, {%0,%1,%2,%3};"
        : "+f"(c[0]), "+f"(c[1]), "+f"(c[2]), "+f"(c[3])
        : "r"(a[0]), "r"(a[1]), "r"(a[2]), "r"(a[3]), "r"(b[0]), "r"(b[1]));
}
__device__ __forceinline__ float sigm(float x) { return 1.f / (1.f + __expf(-x)); }
__device__ __forceinline__ float tanh_(float x) { return 2.f * sigm(2.f * x) - 1.f; }

// Packed column mapping: np -> original gate row n.
// Per 16-col block: [i0 f0 i1 f1 i2 f2 i3 f3 g0 o0 g1 o1 g2 o2 g3 o3]
__device__ __forceinline__ int np_to_n(int np) {
    int r = np & 15, q = r & 7;
    int gate = (r >> 3) * 2 + (q & 1);
    int j = (np >> 4) * 4 + (q >> 1);
    return gate * HID + j;
}

// ---------------- setup / pack ----------------
__global__ void pack_w_kernel(const float* __restrict__ W_ih,
                              const float* __restrict__ W_hh) {
    int idx = blockIdx.x * blockDim.x + threadIdx.x;
    if (idx >= GATES * KTOT) return;
    int np = idx / KTOT;
    int k  = idx - np * KTOT;
    int n = np_to_n(np);
    float v = (k < DIM) ? W_ih[n * DIM + k] : W_hh[(size_t)n * HID + (k - DIM)];
    bf16 hi = __float2bfloat16(v);
    g_Whi[idx] = hi;
    g_Wlo[idx] = __float2bfloat16(v - __bfloat162float(hi));
}

__global__ void pack_src_kernel(const float* __restrict__ src, int srclen) {
    int idx = blockIdx.x * blockDim.x + threadIdx.x;
    if (idx >= srclen * BATCH * DIM) return;
    int s = idx / (BATCH * DIM);
    int rem = idx - s * (BATCH * DIM);
    int b = rem / DIM, d = rem - b * DIM;
    float v = src[((size_t)b * srclen + s) * DIM + d];
    bf16 hi = __float2bfloat16(v);
    g_src_hi[idx] = hi;
    g_src_lo[idx] = __float2bfloat16(v - __bfloat162float(hi));
}

__global__ void setup_kernel(const float* __restrict__ b_ih,
                             const float* __restrict__ b_hh,
                             const float* __restrict__ W_out) {
    int idx = blockIdx.x * blockDim.x + threadIdx.x;
    if (idx < GATES) {
        int n = np_to_n(idx);
        g_b2[idx] = b_ih[n] + b_hh[n];
    }
    if (idx < HID * DIM) {
        int k = idx / DIM, d = idx - k * DIM;
        g_WoutT[idx] = W_out[d * HID + k];
    }
    if (idx < BATCH * HID) {
        g_h_hi[0][idx] = __float2bfloat16(0.f);
        g_h_lo[0][idx] = __float2bfloat16(0.f);
        g_c[idx] = 0.f;
    }
}

// ---------------- fused LSTM step via mma.sync ----------------
// Smem tiles in 8x8-block-linear layout: addr(row,kc) = ((row>>3)*4 + kc)*128 + (row&7)*16
__device__ __forceinline__ void load_stage(int s, int tid, int m0, int n0, uint32_t sm,
                                           const bf16* xh, const bf16* xl,
                                           const bf16* hh, const bf16* hl) {
    uint32_t sb = sm + (uint32_t)(s & 3) * STG_BYTES;
    int k0 = s * 32;
    const bf16 *Ah, *Al; int astr;
    if (k0 < DIM) { Ah = xh + k0;         Al = xl + k0;         astr = DIM; }
    else          { Ah = hh + (k0 - DIM); Al = hl + (k0 - DIM); astr = HID; }
    const bf16* Bh = g_Whi + (size_t)n0 * KTOT + k0;
    const bf16* Bl = g_Wlo + (size_t)n0 * KTOT + k0;
#pragma unroll
    for (int i = 0; i < 2; i++) {
        int c = tid + i * 256;               // 0..511
        int row = c >> 2, kc = c & 3;
        uint32_t off = (uint32_t)(((row >> 3) * 4 + kc) * 128 + (row & 7) * 16);
        size_t arow = (size_t)(m0 + row) * astr + kc * 8;
        size_t brow = (size_t)row * KTOT + kc * 8;
        cp16(sb + off,          Ah + arow);
        cp16(sb + 8192 + off,   Al + arow);
        cp16(sb + 16384 + off,  Bh + brow);
        cp16(sb + 24576 + off,  Bl + brow);
    }
    cp_commit();
}

__global__ __launch_bounds__(256, 1)
void lstm_step_mma(int xmode, int frame, int sel) {
    extern __shared__ uint8_t dsm[];
    uint32_t sm = smem_u32(dsm);

    int tid = threadIdx.x;
    int l = tid & 31, w = tid >> 5;
    int warp_m = w >> 2, warp_n = w & 3;
    int m0 = blockIdx.y * 128;
    int n0 = blockIdx.x * 128;

    const bf16* xh = (xmode == 0) ? (g_src_hi + (size_t)frame * BATCH * DIM)
                                  : (g_dec_hi + (size_t)frame * BATCH * DIM);
    const bf16* xl = (xmode == 0) ? (g_src_lo + (size_t)frame * BATCH * DIM)
                                  : (g_dec_lo + (size_t)frame * BATCH * DIM);
    const bf16* hh = g_h_hi[sel];
    const bf16* hl = g_h_lo[sel];
    bf16* oh = g_h_hi[sel ^ 1];
    bf16* ol = g_h_lo[sel ^ 1];

    float acc[4][4][4];
#pragma unroll
    for (int a = 0; a < 4; a++)
#pragma unroll
        for (int b = 0; b < 4; b++)
#pragma unroll
            for (int c = 0; c < 4; c++) acc[a][b][c] = 0.f;

    // ldmatrix per-thread base offsets (block-linear addressing)
    int aRow = warp_m * 64 + ((l >> 3) & 1) * 8 + (l & 7);
    uint32_t aoff0 = (uint32_t)((aRow >> 3) * 512 + (l >> 4) * 128 + (l & 7) * 16);
    int bRow = warp_n * 32 + ((l >> 4) & 1) * 8 + (l & 7);
    uint32_t boff0 = (uint32_t)((bRow >> 3) * 512 + ((l >> 3) & 1) * 128 + (l & 7) * 16);

    load_stage(0, tid, m0, n0, sm, xh, xl, hh, hl);
    load_stage(1, tid, m0, n0, sm, xh, xl, hh, hl);
    load_stage(2, tid, m0, n0, sm, xh, xl, hh, hl);

#pragma unroll 1
    for (int s = 0; s < NSTAGE; s++) {
        cp_wait<2>();
        __syncthreads();
        uint32_t sb = sm + (uint32_t)(s & 3) * STG_BYTES;
#pragma unroll
        for (int kk = 0; kk < 2; kk++) {
            uint32_t ab  = sb + aoff0 + kk * 256;
            uint32_t bbh = sb + 16384 + boff0 + kk * 256;
            uint32_t Ahf[4][4], Alf[4][4], Bhf[2][4], Blf[2][4];
#pragma unroll
            for (int mi = 0; mi < 4; mi++) {
                ldm4(Ahf[mi], ab + mi * 1024);
                ldm4(Alf[mi], ab + 8192 + mi * 1024);
            }
#pragma unroll
            for (int p = 0; p < 2; p++) {
                ldm4(Bhf[p], bbh + p * 1024);
                ldm4(Blf[p], bbh + 8192 + p * 1024);
            }
#pragma unroll
            for (int mi = 0; mi < 4; mi++)
#pragma unroll
                for (int ni = 0; ni < 4; ni++) {
                    const uint32_t* bh = &Bhf[ni >> 1][(ni & 1) * 2];
                    const uint32_t* bl = &Blf[ni >> 1][(ni & 1) * 2];
                    mma16816(acc[mi][ni], Ahf[mi], bh);   // hi*hi
                    mma16816(acc[mi][ni], Ahf[mi], bl);   // hi*lo
                    mma16816(acc[mi][ni], Alf[mi], bh);   // lo*hi
                }
        }
        if (s + 3 < NSTAGE) load_stage(s + 3, tid, m0, n0, sm, xh, xl, hh, hl);
        else cp_commit();
    }

    // ---- epilogue: LSTM cell, all gates in-register ----
    int t4 = l & 3, rowlo = l >> 2;
    int nb0 = n0 + warp_n * 32;
    float bi[2], bff[2], bg[2], bo[2];
#pragma unroll
    for (int blk = 0; blk < 2; blk++) {
        int nb = nb0 + blk * 16;
        float2 v1 = *(const float2*)&g_b2[nb + 2 * t4];
        float2 v2 = *(const float2*)&g_b2[nb + 8 + 2 * t4];
        bi[blk] = v1.x; bff[blk] = v1.y; bg[blk] = v2.x; bo[blk] = v2.y;
    }
    int jbase = (nb0 >> 4) * 4 + t4;
#pragma unroll
    for (int mi = 0; mi < 4; mi++) {
#pragma unroll
        for (int hr = 0; hr < 2; hr++) {
            int m = m0 + warp_m * 64 + mi * 16 + rowlo + 8 * hr;
            size_t mrow = (size_t)m * HID;
#pragma unroll
            for (int blk = 0; blk < 2; blk++) {
                int j = jbase + blk * 4;
                float gi = acc[mi][2 * blk][2 * hr]         + bi[blk];
                float gf = acc[mi][2 * blk][2 * hr + 1]     + bff[blk];
                float gg = acc[mi][2 * blk + 1][2 * hr]     + bg[blk];
                float go = acc[mi][2 * blk + 1][2 * hr + 1] + bo[blk];
                float cold = g_c[mrow + j];
                float cn = sigm(gf) * cold + sigm(gi) * tanh_(gg);
                float hn = sigm(go) * tanh_(cn);
                g_c[mrow + j] = cn;
                bf16 hi = __float2bfloat16(hn);
                oh[mrow + j] = hi;
                ol[mrow + j] = __float2bfloat16(hn - __bfloat162float(hi));
            }
        }
    }
}

// ---------------- output projection ----------------
#define OBM 16
#define OBN 32
#define OBK 16

__global__ __launch_bounds__(128)
void out_proj_kernel(int sel, const float* __restrict__ b_out,
                     float* __restrict__ out, int ostride, int t) {
    __shared__ float As[OBK][OBM];
    __shared__ float Bs[OBK][OBN];

    const bf16* __restrict__ hh = g_h_hi[sel];
    const bf16* __restrict__ hl = g_h_lo[sel];

    int tid = threadIdx.x;
    int tm = tid >> 3;
    int tn = tid & 7;
    int m0 = blockIdx.y * OBM;
    int n0 = blockIdx.x * OBN;

    int a_m  = tid >> 3;
    int a_k2 = (tid & 7) * 2;
    int b_k = tid >> 5;
    int b_n = tid & 31;

    float acc[4] = {0.f, 0.f, 0.f, 0.f};

    for (int k0 = 0; k0 < HID; k0 += OBK) {
        size_t aoff = (size_t)(m0 + a_m) * HID + k0 + a_k2;
        __nv_bfloat162 vh = *(const __nv_bfloat162*)(hh + aoff);
        __nv_bfloat162 vl = *(const __nv_bfloat162*)(hl + aoff);
        float av0 = __bfloat162float(vh.x) + __bfloat162float(vl.x);
        float av1 = __bfloat162float(vh.y) + __bfloat162float(vl.y);
        float bv[4];
#pragma unroll
        for (int i = 0; i < 4; i++)
            bv[i] = g_WoutT[(size_t)(k0 + b_k + 4 * i) * DIM + n0 + b_n];

        __syncthreads();
        As[a_k2][a_m]     = av0;
        As[a_k2 + 1][a_m] = av1;
#pragma unroll
        for (int i = 0; i < 4; i++) Bs[b_k + 4 * i][b_n] = bv[i];
        __syncthreads();

#pragma unroll
        for (int kk = 0; kk < OBK; kk++) {
            float a = As[kk][tm];
            float b[4];
            *(float4*)&b[0] = *(const float4*)&Bs[kk][tn * 4];
#pragma unroll
            for (int c2 = 0; c2 < 4; c2++) acc[c2] += a * b[c2];
        }
    }

    bf16* dh = g_dec_hi + (size_t)t * BATCH * DIM;
    bf16* dl = g_dec_lo + (size_t)t * BATCH * DIM;
#pragma unroll
    for (int c2 = 0; c2 < 4; c2++) {
        int n = n0 + tn * 4 + c2;
        int m = m0 + tm;
        float v = acc[c2] + b_out[n];
        out[(size_t)m * ostride + n] = v;
        bf16 hi = __float2bfloat16(v);
        dh[m * DIM + n] = hi;
        dl[m * DIM + n] = __float2bfloat16(v - __bfloat162float(hi));
    }
}

// ---------------- launch ----------------
extern "C" void kernel_launch(void* const* d_in, const int* in_sizes, int n_in,
                              void* d_out, int out_size) {
    const float* src   = (const float*)d_in[0];
    const float* W_ih  = (const float*)d_in[2];
    const float* W_hh  = (const float*)d_in[3];
    const float* b_ih  = (const float*)d_in[4];
    const float* b_hh  = (const float*)d_in[5];
    const float* W_out = (const float*)d_in[6];
    const float* b_out = (const float*)d_in[7];
    float* out = (float*)d_out;

    int srclen = in_sizes[0] / (BATCH * DIM);   // 240
    int tgtlen = in_sizes[1] / (BATCH * DIM);   // 24
    int ostride = tgtlen * DIM;

    static int attr_done = 0;
    if (!attr_done) {
        cudaFuncSetAttribute(lstm_step_mma, cudaFuncAttributeMaxDynamicSharedMemorySize, SMEM_REQ);
        attr_done = 1;
    }

    pack_w_kernel<<<(GATES * KTOT + 255) / 256, 256>>>(W_ih, W_hh);
    pack_src_kernel<<<(srclen * BATCH * DIM + 255) / 256, 256>>>(src, srclen);
    setup_kernel<<<(BATCH * HID + 255) / 256, 256>>>(b_ih, b_hh, W_out);

    dim3 sgrid(GATES / 128, BATCH / 128);   // (32, 4)
    dim3 ogrid(DIM / OBN, BATCH / OBM);     // (4, 32)

    int sel = 0;
    for (int t = 0; t < srclen - 1; t++) {
        lstm_step_mma<<<sgrid, 256, SMEM_REQ>>>(0, t, sel);
        sel ^= 1;
    }
    for (int t = 0; t < tgtlen; t++) {
        if (t == 0) lstm_step_mma<<<sgrid, 256, SMEM_REQ>>>(0, srclen - 1, sel);
        else        lstm_step_mma<<<sgrid, 256, SMEM_REQ>>>(1, t - 1, sel);
        sel ^= 1;
        out_proj_kernel<<<ogrid, 128>>>(sel, b_out, out + (size_t)t * DIM, ostride, t);
    }
}